// round 2
// baseline (speedup 1.0000x reference)
#include <cuda_runtime.h>
#include <cstdint>

#define BATCH   8192
#define DIM     1024
#define NCLASS  1000
#define CPAD    1024
#define N_PAIRS 499500.0f   // 1000*999/2

// ---------------- scratch (device globals) ----------------
__device__ float g_invnorm[BATCH];
__device__ int   g_counts[CPAD];
__device__ int   g_offsets[CPAD];
__device__ int   g_cursor[CPAD];
__device__ int   g_perm[BATCH];
__device__ float g_centers_new[CPAD * DIM];   // rows >= NCLASS never written -> stay 0
__device__ float g_sq[CPAD];                  // entries >= NCLASS never written -> stay 0
__device__ float g_accum[2];                  // [0]=intra sum, [1]=inter sum
__device__ int   g_lab64;

// ---------------- helpers ----------------
__device__ __forceinline__ int read_label(const void* labels, int b) {
    const int* w = (const int*)labels;
    int v = g_lab64 ? w[2 * b] : w[b];   // little-endian low word of int64 == value
    // safety clamp: keeps all scratch indexing in-bounds even under mis-decode
    return (v >= 0 && v < NCLASS) ? v : 0;
}

__device__ __forceinline__ float warp_sum(float v) {
    #pragma unroll
    for (int o = 16; o; o >>= 1) v += __shfl_xor_sync(0xffffffffu, v, o);
    return v;
}

// ---------------- kernels ----------------
__global__ void k_init(const void* labels) {
    int t = blockIdx.x * blockDim.x + threadIdx.x;
    if (t < CPAD) g_counts[t] = 0;
    if (t < 2)    g_accum[t] = 0.0f;
    // label-width probe: one warp checks 32 odd 32-bit words in parallel.
    // int64 labels (<2^31) -> all odd words zero; int32 random labels -> almost
    // surely some nonzero. 32 samples of U(0,1000) all being zero ~ 1e-96.
    if (blockIdx.x == 0 && t < 32) {
        const int* w = (const int*)labels;
        unsigned nz = __ballot_sync(0xffffffffu, w[2 * t + 1] != 0);
        if (t == 0) g_lab64 = (nz == 0u);
    }
}

// one warp per row: inv-norm of features + class counts
__global__ void k_norms(const float* __restrict__ f, const void* __restrict__ labels) {
    int warp = threadIdx.x >> 5, lane = threadIdx.x & 31;
    int row = blockIdx.x * 8 + warp;
    const float4* fr = (const float4*)(f + (size_t)row * DIM);
    float ss = 0.0f;
    #pragma unroll
    for (int q = 0; q < 8; q++) {
        float4 v = fr[q * 32 + lane];
        ss += v.x * v.x + v.y * v.y + v.z * v.z + v.w * v.w;
    }
    ss = warp_sum(ss);
    if (lane == 0) {
        g_invnorm[row] = 1.0f / fmaxf(sqrtf(ss), 1e-12f);
        atomicAdd(&g_counts[read_label(labels, row)], 1);
    }
}

// exclusive scan of counts (single block, 1024 threads)
__global__ void k_scan() {
    __shared__ int s[CPAD];
    int t = threadIdx.x;
    int c = (t < NCLASS) ? g_counts[t] : 0;
    s[t] = c;
    __syncthreads();
    for (int off = 1; off < CPAD; off <<= 1) {
        int add = (t >= off) ? s[t - off] : 0;
        __syncthreads();
        s[t] += add;
        __syncthreads();
    }
    int excl = s[t] - c;
    g_offsets[t] = excl;
    g_cursor[t]  = excl;
}

__global__ void k_scatter(const void* __restrict__ labels) {
    int b = blockIdx.x * blockDim.x + threadIdx.x;
    if (b < BATCH) {
        int pos = atomicAdd(&g_cursor[read_label(labels, b)], 1);
        if (pos >= 0 && pos < BATCH) g_perm[pos] = b;
    }
}

// one block (256 threads) per class: momentum center update + ||c_new||^2
__global__ void k_update(const float* __restrict__ f, const float* __restrict__ centers) {
    int c = blockIdx.x;
    int t = threadIdx.x;
    int start = g_offsets[c];
    int cnt   = g_counts[c];

    float4 acc = {0.f, 0.f, 0.f, 0.f};
    for (int i = 0; i < cnt; i++) {
        int r = g_perm[start + i];
        float inv = g_invnorm[r];
        float4 v = *(const float4*)(f + (size_t)r * DIM + t * 4);
        acc.x += v.x * inv; acc.y += v.y * inv; acc.z += v.z * inv; acc.w += v.w * inv;
    }
    float rc = 1.0f / fmaxf((float)cnt, 1.0f);
    float4 mean = {acc.x * rc, acc.y * rc, acc.z * rc, acc.w * rc};
    float4 co = *(const float4*)(centers + (size_t)c * DIM + t * 4);

    int zflag = (co.x == 0.f && co.y == 0.f && co.z == 0.f && co.w == 0.f);
    int allz = __syncthreads_and(zflag);

    float4 outv;
    if (cnt > 0) {
        if (allz) outv = mean;
        else {
            outv.x = 0.9f * co.x + 0.1f * mean.x;
            outv.y = 0.9f * co.y + 0.1f * mean.y;
            outv.z = 0.9f * co.z + 0.1f * mean.z;
            outv.w = 0.9f * co.w + 0.1f * mean.w;
        }
    } else outv = co;

    *(float4*)(g_centers_new + (size_t)c * DIM + t * 4) = outv;

    float s = outv.x * outv.x + outv.y * outv.y + outv.z * outv.z + outv.w * outv.w;
    s = warp_sum(s);
    __shared__ float ws[8];
    if ((t & 31) == 0) ws[t >> 5] = s;
    __syncthreads();
    if (t == 0) {
        float tot = 0.f;
        #pragma unroll
        for (int w = 0; w < 8; w++) tot += ws[w];
        g_sq[c] = tot;
    }
}

// one warp per row: intra-class distances for clean + adv features
__global__ void k_intra(const float* __restrict__ f, const float* __restrict__ fa,
                        const void* __restrict__ labels) {
    int warp = threadIdx.x >> 5, lane = threadIdx.x & 31;
    int b = blockIdx.x * 8 + warp;
    int lab = read_label(labels, b);

    const float4* fr  = (const float4*)(f  + (size_t)b * DIM);
    const float4* far = (const float4*)(fa + (size_t)b * DIM);
    const float4* cr  = (const float4*)(g_centers_new + (size_t)lab * DIM);

    float df = 0.f, dfa = 0.f, ssa = 0.f;
    #pragma unroll
    for (int q = 0; q < 8; q++) {
        float4 v  = fr[q * 32 + lane];
        float4 va = far[q * 32 + lane];
        float4 cv = cr[q * 32 + lane];
        df  += v.x * cv.x + v.y * cv.y + v.z * cv.z + v.w * cv.w;
        dfa += va.x * cv.x + va.y * cv.y + va.z * cv.z + va.w * cv.w;
        ssa += va.x * va.x + va.y * va.y + va.z * va.z + va.w * va.w;
    }
    df  = warp_sum(df);
    dfa = warp_sum(dfa);
    ssa = warp_sum(ssa);

    __shared__ float bsum;
    if (threadIdx.x == 0) bsum = 0.f;
    __syncthreads();
    if (lane == 0) {
        float invf  = g_invnorm[b];
        float invfa = 1.0f / fmaxf(sqrtf(ssa), 1e-12f);
        float sqc = g_sq[lab];
        float d1 = sqrtf(fmaxf(1.0f - 2.0f * df  * invf  + sqc, 0.0f));
        float d2 = sqrtf(fmaxf(1.0f - 2.0f * dfa * invfa + sqc, 0.0f));
        atomicAdd(&bsum, d1 + d2);
    }
    __syncthreads();
    if (threadIdx.x == 0) atomicAdd(&g_accum[0], bsum);
}

// pairwise-center GEMM over upper-triangular 64x64 tiles, fused relu(1-dist) reduction
#define KTILE 32
#define TSTRIDE 68   // 64 + 4 pad, keeps float4 alignment + spreads banks
__global__ void k_gemm() {
    __shared__ __align__(16) float As[KTILE][TSTRIDE];
    __shared__ __align__(16) float Bs[KTILE][TSTRIDE];

    // map linear block id -> (ti, tj), ti <= tj, 16 tile rows
    int rem = blockIdx.x;
    int ti = 0;
    while (rem >= 16 - ti) { rem -= 16 - ti; ti++; }
    int tj = ti + rem;
    int ibase = ti * 64, jbase = tj * 64;

    int t = threadIdx.x;
    int i0 = (t & 15) * 4;
    int j0 = (t >> 4) * 4;
    float acc[4][4] = {};

    for (int k0 = 0; k0 < DIM; k0 += KTILE) {
        #pragma unroll
        for (int p = 0; p < 2; p++) {
            int idx = t + p * 256;
            int row = idx >> 3;   // 0..63
            int kq  = idx & 7;    // 0..7
            float4 a = *(const float4*)(g_centers_new + (size_t)(ibase + row) * DIM + k0 + kq * 4);
            float4 b = *(const float4*)(g_centers_new + (size_t)(jbase + row) * DIM + k0 + kq * 4);
            As[kq * 4 + 0][row] = a.x; As[kq * 4 + 1][row] = a.y;
            As[kq * 4 + 2][row] = a.z; As[kq * 4 + 3][row] = a.w;
            Bs[kq * 4 + 0][row] = b.x; Bs[kq * 4 + 1][row] = b.y;
            Bs[kq * 4 + 2][row] = b.z; Bs[kq * 4 + 3][row] = b.w;
        }
        __syncthreads();
        #pragma unroll
        for (int k = 0; k < KTILE; k++) {
            float4 a4 = *(const float4*)&As[k][i0];
            float4 b4 = *(const float4*)&Bs[k][j0];
            float av[4] = {a4.x, a4.y, a4.z, a4.w};
            float bv[4] = {b4.x, b4.y, b4.z, b4.w};
            #pragma unroll
            for (int di = 0; di < 4; di++)
                #pragma unroll
                for (int dj = 0; dj < 4; dj++)
                    acc[di][dj] = fmaf(av[di], bv[dj], acc[di][dj]);
        }
        __syncthreads();
    }

    float local = 0.f;
    #pragma unroll
    for (int di = 0; di < 4; di++) {
        #pragma unroll
        for (int dj = 0; dj < 4; dj++) {
            int i = ibase + i0 + di;
            int j = jbase + j0 + dj;
            if (i < j && j < NCLASS) {
                float d2 = g_sq[i] + g_sq[j] - 2.0f * acc[di][dj];
                float d  = sqrtf(fmaxf(d2, 0.0f));
                local += fmaxf(1.0f - d, 0.0f);
            }
        }
    }
    local = warp_sum(local);
    __shared__ float ws[8];
    if ((t & 31) == 0) ws[t >> 5] = local;
    __syncthreads();
    if (t == 0) {
        float tot = 0.f;
        #pragma unroll
        for (int w = 0; w < 8; w++) tot += ws[w];
        atomicAdd(&g_accum[1], tot);
    }
}

__global__ void k_final(float* out) {
    float intra = g_accum[0] / (float)BATCH;     // intra_clean + intra_adv (means share /BATCH)
    float inter = g_accum[1] / N_PAIRS;
    out[0] = intra - 0.5f * inter;               // LAMBDA_INTRA=1, LAMBDA_INTER=0.5
}

// ---------------- launch ----------------
extern "C" void kernel_launch(void* const* d_in, const int* in_sizes, int n_in,
                              void* d_out, int out_size) {
    const float* f       = (const float*)d_in[0];
    const float* fa      = (const float*)d_in[1];
    const float* centers = (const float*)d_in[2];
    const void*  labels  = d_in[3];
    float* out = (float*)d_out;

    k_init<<<4, 256>>>(labels);
    k_norms<<<BATCH / 8, 256>>>(f, labels);
    k_scan<<<1, 1024>>>();
    k_scatter<<<BATCH / 256, 256>>>(labels);
    k_update<<<NCLASS, 256>>>(f, centers);
    k_intra<<<BATCH / 8, 256>>>(f, fa, labels);
    k_gemm<<<136, 256>>>();
    k_final<<<1, 1>>>(out);
}